// round 17
// baseline (speedup 1.0000x reference)
#include <cuda_runtime.h>
#include <cuda_bf16.h>
#include <cuda_fp16.h>
#include <math_constants.h>
#include <cstdint>

#define N_NODES 50000
#define N_EDGES 800000
#define D 128
#define N_GRAPHS 64
#define SCAN_BLK 1024
#define N_SCAN_BLKS ((N_NODES + SCAN_BLK - 1) / SCAN_BLK)   // 49
#define POOL_CHUNKS 8

// GEMM smem layout in uint32 units, plain bf16 tiles (ldmatrix-friendly).
#define WSTRB 68
#define WBUFB (16 * WSTRB)       // 1088
#define ASTRB 12
#define ABUFB (128 * ASTRB)      // 1536
#define S_WH 0
#define S_WL (2 * WBUFB)
#define S_AH (4 * WBUFB)
#define S_AL (4 * WBUFB + 2 * ABUFB)
#define S_TOT (4 * WBUFB + 4 * ABUFB)      // 10496 u32 = 41984 B

// ------------------------- device scratch ----------------------------------
__device__ float    g_dis[N_NODES];
__device__ int      g_deg[N_NODES];         // zeroed by k_scanL for next call
__device__ int      g_rowoff[N_NODES + 1];
__device__ int      g_next[N_NODES];
__device__ unsigned long long g_tile[N_SCAN_BLKS];   // lookback status (flag<<32|val)
__device__ int      g_col[N_EDGES];
__device__ uint32_t g_h16[N_NODES * 64];    // GEMM output, half2 packed (feeds agg)
__device__ uint32_t g_a16[N_NODES * 64];    // agg output, half2 packed (feeds GEMM)
__device__ float    g_agg[N_NODES * D];     // layer-3 agg output (fp32, feeds pool)
__device__ float    g_pmax[N_GRAPHS * POOL_CHUNKS * D];
__device__ uint32_t g_Wbh[3 * 128 * 64];    // plain bf16 hi W, [layer][k][n2]
__device__ uint32_t g_Wbl[3 * 128 * 64];    // plain bf16 lo W

// ------------------------- helpers -----------------------------------------
__device__ __forceinline__ void split_pack(float x, float y,
                                           uint32_t& hi, uint32_t& lo) {
    __nv_bfloat162 h2 = __floats2bfloat162_rn(x, y);
    float rx = x - __bfloat162float(h2.x);
    float ry = y - __bfloat162float(h2.y);
    __nv_bfloat162 l2 = __floats2bfloat162_rn(rx, ry);
    hi = *reinterpret_cast<uint32_t*>(&h2);
    lo = *reinterpret_cast<uint32_t*>(&l2);
}

__device__ __forceinline__ uint32_t pack_h2(float a, float b) {
    __half2 h = __floats2half2_rn(a, b);
    return *reinterpret_cast<uint32_t*>(&h);
}

#define MMA_BF16(C, A0, A1, A2, A3, B0, B1)                                   \
    asm volatile(                                                             \
        "mma.sync.aligned.m16n8k16.row.col.f32.bf16.bf16.f32 "                \
        "{%0,%1,%2,%3}, {%4,%5,%6,%7}, {%8,%9}, {%0,%1,%2,%3};"               \
        : "+f"(C[0]), "+f"(C[1]), "+f"(C[2]), "+f"(C[3])                      \
        : "r"(A0), "r"(A1), "r"(A2), "r"(A3), "r"(B0), "r"(B1))

__device__ __forceinline__ void ldsm_x4(uint32_t& r0, uint32_t& r1,
                                        uint32_t& r2, uint32_t& r3,
                                        uint32_t addr) {
    asm volatile("ldmatrix.sync.aligned.m8n8.x4.shared.b16 {%0,%1,%2,%3}, [%4];"
                 : "=r"(r0), "=r"(r1), "=r"(r2), "=r"(r3) : "r"(addr));
}
__device__ __forceinline__ void ldsm_x4_t(uint32_t& r0, uint32_t& r1,
                                          uint32_t& r2, uint32_t& r3,
                                          uint32_t addr) {
    asm volatile("ldmatrix.sync.aligned.m8n8.x4.trans.shared.b16 {%0,%1,%2,%3}, [%4];"
                 : "=r"(r0), "=r"(r1), "=r"(r2), "=r"(r3) : "r"(addr));
}

__device__ __forceinline__ void cp_async16u(uint32_t* dst_smem, const uint32_t* src) {
    unsigned d = (unsigned)__cvta_generic_to_shared(dst_smem);
    asm volatile("cp.async.cg.shared.global [%0], [%1], 16;" :: "r"(d), "l"(src));
}
__device__ __forceinline__ void cp_commit() {
    asm volatile("cp.async.commit_group;");
}
__device__ __forceinline__ void cp_wait0() {
    asm volatile("cp.async.wait_group 0;");
}

// ------------------------- CSR build ---------------------------------------
__global__ void k_count(const int* __restrict__ dst) {
    // block 0 resets lookback status for this invocation's scan
    if (blockIdx.x == 0 && threadIdx.x < N_SCAN_BLKS)
        g_tile[threadIdx.x] = 0ULL;
    int i = blockIdx.x * blockDim.x + threadIdx.x;
    if (i < N_EDGES) atomicAdd(&g_deg[dst[i]], 1);
}

// single-pass decoupled-lookback exclusive scan of g_deg.
// Writes g_rowoff, g_dis, g_next; zeroes g_deg for the next invocation.
__global__ __launch_bounds__(SCAN_BLK) void k_scanL() {
    __shared__ int wsum[32];
    __shared__ int s_tot, s_prefix;
    int t = threadIdx.x;
    int lane = t & 31, warp = t >> 5;
    int b = blockIdx.x;
    int i = b * SCAN_BLK + t;
    int v = (i < N_NODES) ? g_deg[i] : 0;
    int incl = v;
#pragma unroll
    for (int off = 1; off < 32; off <<= 1) {
        int u = __shfl_up_sync(0xffffffffu, incl, off);
        if (lane >= off) incl += u;
    }
    if (lane == 31) wsum[warp] = incl;
    __syncthreads();
    if (warp == 0) {
        int w = wsum[lane];
        int wi = w;
#pragma unroll
        for (int off = 1; off < 32; off <<= 1) {
            int u = __shfl_up_sync(0xffffffffu, wi, off);
            if (lane >= off) wi += u;
        }
        wsum[lane] = wi - w;
    }
    __syncthreads();
    int inclTot = incl + wsum[warp];
    if (t == SCAN_BLK - 1) s_tot = inclTot;
    __syncthreads();

    // warp 0: publish aggregate, lookback for exclusive prefix, publish incl.
    if (warp == 0) {
        int tot = s_tot;
        if (lane == 0) {
            unsigned long long pack = (b == 0)
                ? ((2ULL << 32) | (unsigned)tot)
                : ((1ULL << 32) | (unsigned)tot);
            atomicExch(&g_tile[b], pack);
        }
        int prefix = 0;
        if (b > 0) {
            int look = b - 1;
            while (true) {
                int idx = look - lane;
                int f; unsigned val;
                if (idx >= 0) {
                    unsigned long long st;
                    do {
                        st = *(volatile unsigned long long*)&g_tile[idx];
                        f = (int)(st >> 32);
                    } while (f == 0);
                    val = (unsigned)st;
                } else { f = 2; val = 0; }
                unsigned m2 = __ballot_sync(0xffffffffu, f == 2);
                int c;
                if (m2) {
                    int L = __ffs(m2) - 1;          // nearest block with inclusive
                    c = (lane <= L) ? (int)val : 0;
                } else {
                    c = (int)val;
                }
#pragma unroll
                for (int o = 16; o; o >>= 1) c += __shfl_down_sync(0xffffffffu, c, o);
                c = __shfl_sync(0xffffffffu, c, 0);
                prefix += c;
                if (m2) break;
                look -= 32;
            }
            if (lane == 0)
                atomicExch(&g_tile[b], (2ULL << 32) | (unsigned)(prefix + tot));
        }
        if (lane == 0) s_prefix = prefix;
    }
    __syncthreads();
    int boff = s_prefix;
    if (i < N_NODES) {
        int fin = boff + inclTot - v;
        g_rowoff[i] = fin;
        g_next[i] = fin;
        g_dis[i] = rsqrtf((float)v + 1.0f);
        g_deg[i] = 0;                   // ready for next invocation
    }
    if (i == 0) g_rowoff[N_NODES] = N_EDGES;
}

__global__ void k_fill(const int* __restrict__ src, const int* __restrict__ dst) {
    int i = blockIdx.x * blockDim.x + threadIdx.x;
    if (i < N_EDGES) {
        int pos = atomicAdd(&g_next[dst[i]], 1);
        g_col[pos] = src[i];
    }
}

// ------------------------- weight pre-split (plain bf16 hi/lo) -------------
__global__ void k_splitW(const float* __restrict__ W1,
                         const float* __restrict__ W2,
                         const float* __restrict__ W3) {
    int i = blockIdx.x * blockDim.x + threadIdx.x;     // 0..24575
    if (i >= 3 * 128 * 64) return;
    int m = i >> 13, r = i & 8191;
    int k = r >> 6, n2 = r & 63;
    const float* Ws = (m == 0) ? W1 : ((m == 1) ? W2 : W3);
    float x0 = Ws[k * D + 2 * n2];
    float x1 = Ws[k * D + 2 * n2 + 1];
    uint32_t hi, lo;
    split_pack(x0, x1, hi, lo);
    g_Wbh[i] = hi;
    g_Wbl[i] = lo;
}

// ------------------------- pipelined bf16x3 GEMM, templated A dtype --------
// AFP16=0: A is fp32 [N,128]; AFP16=1: A is half2-packed uint32 [N,64].
// 256 threads (8 warps as 4x2), M-tile 128, K chunk 16, double-buffered.
// Epilogue scales row i by dis[i], stores half2-packed h.
template <int AFP16>
__device__ __forceinline__ float4 load_a4(const void* Ag, int gr, int col) {
    if (AFP16) {
        const uint32_t* a16 = (const uint32_t*)Ag;
        uint2 u = *(const uint2*)(a16 + (size_t)gr * 64 + (col >> 1));
        float2 f0 = __half22float2(*reinterpret_cast<__half2*>(&u.x));
        float2 f1 = __half22float2(*reinterpret_cast<__half2*>(&u.y));
        return make_float4(f0.x, f0.y, f1.x, f1.y);
    } else {
        const float* Af = (const float*)Ag;
        return *(const float4*)(Af + (size_t)gr * D + col);
    }
}

template <int AFP16>
__global__ __launch_bounds__(256, 2) void k_gemm_tc(const void* __restrict__ Ag,
                                                    const uint32_t* __restrict__ Wbh,
                                                    const uint32_t* __restrict__ Wbl,
                                                    uint32_t* __restrict__ H16) {
    __shared__ uint32_t sm[S_TOT];
    int tid  = threadIdx.x;
    int warp = tid >> 5, lane = tid & 31;
    int g = lane >> 2, tg = lane & 3;
    int wm = warp & 3, wn = warp >> 2;          // 4x2 warp grid
    int row0 = blockIdx.x * 128;

    int wrr = tid >> 4, wcc = (tid & 15) * 4;   // W: 16 rows x 64 u32
    int ar = tid >> 2;                           // A rows ar, ar+64
    int afc = (tid & 3) * 4;
    int apc = (tid & 3) * 2;

    int rowsel = ((lane >> 3) & 1) * 8 + (lane & 7);
    int half4 = (lane >> 4) * 4;
    uint32_t smb = (uint32_t)__cvta_generic_to_shared(sm);
    uint32_t a_addr[2];
#pragma unroll
    for (int mt = 0; mt < 2; mt++)
        a_addr[mt] = smb + (uint32_t)(S_AH + (wm * 32 + mt * 16 + rowsel) * ASTRB + half4) * 4;
    uint32_t w_addr[4];
#pragma unroll
    for (int p = 0; p < 4; p++)
        w_addr[p] = smb + (uint32_t)(S_WH + rowsel * WSTRB + wn * 32 + p * 8 + half4) * 4;

    const uint32_t ALOFF = (uint32_t)(S_AL - S_AH) * 4;
    const uint32_t WLOFF = (uint32_t)(S_WL - S_WH) * 4;

    float acc[2][8][4];
#pragma unroll
    for (int mt = 0; mt < 2; mt++)
#pragma unroll
        for (int nt = 0; nt < 8; nt++)
#pragma unroll
            for (int c = 0; c < 4; c++) acc[mt][nt][c] = 0.0f;

    // ---- prologue: stage chunk 0 into buffer 0
    cp_async16u(&sm[S_WH + wrr * WSTRB + wcc], Wbh + wrr * 64 + wcc);
    cp_async16u(&sm[S_WL + wrr * WSTRB + wcc], Wbl + wrr * 64 + wcc);
    cp_commit();
#pragma unroll
    for (int p = 0; p < 2; p++) {
        int rr = ar + p * 64;
        int gr = row0 + rr;
        float4 v = make_float4(0.f, 0.f, 0.f, 0.f);
        if (gr < N_NODES) v = load_a4<AFP16>(Ag, gr, afc);
        uint32_t h0, l0, h1, l1;
        split_pack(v.x, v.y, h0, l0);
        split_pack(v.z, v.w, h1, l1);
        *(uint2*)&sm[S_AH + rr * ASTRB + apc] = make_uint2(h0, h1);
        *(uint2*)&sm[S_AL + rr * ASTRB + apc] = make_uint2(l0, l1);
    }
    cp_wait0();
    __syncthreads();

    for (int kc = 0; kc < 8; kc++) {
        int buf = kc & 1, nxt = buf ^ 1;
        bool pre = (kc < 7);
        float4 v0, v1;
        if (pre) {
            const uint32_t* wh = Wbh + (kc + 1) * 1024;
            const uint32_t* wl = Wbl + (kc + 1) * 1024;
            cp_async16u(&sm[S_WH + nxt * WBUFB + wrr * WSTRB + wcc], wh + wrr * 64 + wcc);
            cp_async16u(&sm[S_WL + nxt * WBUFB + wrr * WSTRB + wcc], wl + wrr * 64 + wcc);
            cp_commit();
            int kcol = (kc + 1) * 16 + afc;
            v0 = make_float4(0.f, 0.f, 0.f, 0.f); v1 = v0;
            int gr0 = row0 + ar, gr1 = gr0 + 64;
            if (gr0 < N_NODES) v0 = load_a4<AFP16>(Ag, gr0, kcol);
            if (gr1 < N_NODES) v1 = load_a4<AFP16>(Ag, gr1, kcol);
        }

        uint32_t abufo = (uint32_t)(buf * ABUFB) * 4;
        uint32_t wbufo = (uint32_t)(buf * WBUFB) * 4;

        uint32_t ah[2][4], al[2][4];
#pragma unroll
        for (int mt = 0; mt < 2; mt++) {
            ldsm_x4(ah[mt][0], ah[mt][1], ah[mt][2], ah[mt][3], a_addr[mt] + abufo);
            ldsm_x4(al[mt][0], al[mt][1], al[mt][2], al[mt][3], a_addr[mt] + abufo + ALOFF);
        }
#pragma unroll
        for (int p = 0; p < 4; p++) {
            uint32_t bh0, bh1, bh2, bh3, bl0, bl1, bl2, bl3;
            ldsm_x4_t(bh0, bh1, bh2, bh3, w_addr[p] + wbufo);
            ldsm_x4_t(bl0, bl1, bl2, bl3, w_addr[p] + wbufo + WLOFF);
            MMA_BF16(acc[0][2 * p],     ah[0][0], ah[0][1], ah[0][2], ah[0][3], bh0, bh1);
            MMA_BF16(acc[1][2 * p],     ah[1][0], ah[1][1], ah[1][2], ah[1][3], bh0, bh1);
            MMA_BF16(acc[0][2 * p + 1], ah[0][0], ah[0][1], ah[0][2], ah[0][3], bh2, bh3);
            MMA_BF16(acc[1][2 * p + 1], ah[1][0], ah[1][1], ah[1][2], ah[1][3], bh2, bh3);
            MMA_BF16(acc[0][2 * p],     ah[0][0], ah[0][1], ah[0][2], ah[0][3], bl0, bl1);
            MMA_BF16(acc[1][2 * p],     ah[1][0], ah[1][1], ah[1][2], ah[1][3], bl0, bl1);
            MMA_BF16(acc[0][2 * p + 1], ah[0][0], ah[0][1], ah[0][2], ah[0][3], bl2, bl3);
            MMA_BF16(acc[1][2 * p + 1], ah[1][0], ah[1][1], ah[1][2], ah[1][3], bl2, bl3);
            MMA_BF16(acc[0][2 * p],     al[0][0], al[0][1], al[0][2], al[0][3], bh0, bh1);
            MMA_BF16(acc[1][2 * p],     al[1][0], al[1][1], al[1][2], al[1][3], bh0, bh1);
            MMA_BF16(acc[0][2 * p + 1], al[0][0], al[0][1], al[0][2], al[0][3], bh2, bh3);
            MMA_BF16(acc[1][2 * p + 1], al[1][0], al[1][1], al[1][2], al[1][3], bh2, bh3);
        }

        if (pre) {
            uint32_t h0, l0, h1, l1;
            split_pack(v0.x, v0.y, h0, l0);
            split_pack(v0.z, v0.w, h1, l1);
            *(uint2*)&sm[S_AH + nxt * ABUFB + ar * ASTRB + apc] = make_uint2(h0, h1);
            *(uint2*)&sm[S_AL + nxt * ABUFB + ar * ASTRB + apc] = make_uint2(l0, l1);
            split_pack(v1.x, v1.y, h0, l0);
            split_pack(v1.z, v1.w, h1, l1);
            *(uint2*)&sm[S_AH + nxt * ABUFB + (ar + 64) * ASTRB + apc] = make_uint2(h0, h1);
            *(uint2*)&sm[S_AL + nxt * ABUFB + (ar + 64) * ASTRB + apc] = make_uint2(l0, l1);
            cp_wait0();
            __syncthreads();
        }
    }

    // ---- epilogue: scale row r by dis[r], store half2 pairs
#pragma unroll
    for (int mt = 0; mt < 2; mt++) {
        int r0 = row0 + wm * 32 + mt * 16 + g;
        int r1 = r0 + 8;
        float s0 = (r0 < N_NODES) ? g_dis[r0] : 0.f;
        float s1 = (r1 < N_NODES) ? g_dis[r1] : 0.f;
#pragma unroll
        for (int nt = 0; nt < 8; nt++) {
            int cp2 = wn * 32 + nt * 4 + tg;      // half2 column index
            if (r0 < N_NODES)
                H16[(size_t)r0 * 64 + cp2] = pack_h2(acc[mt][nt][0] * s0,
                                                     acc[mt][nt][1] * s0);
            if (r1 < N_NODES)
                H16[(size_t)r1 * 64 + cp2] = pack_h2(acc[mt][nt][2] * s1,
                                                     acc[mt][nt][3] * s1);
        }
    }
}

// ------------------------- aggregation: one warp per node, fp16 gather -----
// out_i = dis_i * (sum_e h[col_e] + h_i) + b  (ReLU optional).
// mode 1: write half2 pairs (feeds next GEMM). mode 0: write fp32 (pool).
__global__ __launch_bounds__(256) void k_agg(const uint32_t* __restrict__ h16,
                                             const float* __restrict__ b,
                                             float* __restrict__ outf,
                                             uint32_t* __restrict__ o16,
                                             int mode) {
    int lane = threadIdx.x & 31;
    int node = blockIdx.x * (blockDim.x >> 5) + (threadIdx.x >> 5);
    if (node >= N_NODES) return;
    int beg = g_rowoff[node], end = g_rowoff[node + 1];
    const uint2* __restrict__ hp = (const uint2*)h16;   // 4 halves per uint2
    float4 acc;
    {
        uint2 v = hp[(size_t)node * 32 + lane];
        float2 fa = __half22float2(*reinterpret_cast<__half2*>(&v.x));
        float2 fc = __half22float2(*reinterpret_cast<__half2*>(&v.y));
        acc = make_float4(fa.x, fa.y, fc.x, fc.y);
    }
    for (int e0 = beg; e0 < end; e0 += 32) {
        int n = min(32, end - e0);
        int c = (lane < n) ? g_col[e0 + lane] : 0;
        int j = 0;
        for (; j + 8 <= n; j += 8) {
            int cj[8];
#pragma unroll
            for (int u = 0; u < 8; u++) cj[u] = __shfl_sync(0xffffffffu, c, j + u);
            uint2 hv[8];
#pragma unroll
            for (int u = 0; u < 8; u++) hv[u] = hp[(size_t)cj[u] * 32 + lane];
#pragma unroll
            for (int u = 0; u < 8; u++) {
                float2 fa = __half22float2(*reinterpret_cast<__half2*>(&hv[u].x));
                float2 fd = __half22float2(*reinterpret_cast<__half2*>(&hv[u].y));
                acc.x += fa.x; acc.y += fa.y;
                acc.z += fd.x; acc.w += fd.y;
            }
        }
        for (; j < n; j++) {
            int cj = __shfl_sync(0xffffffffu, c, j);
            uint2 v = hp[(size_t)cj * 32 + lane];
            float2 fa = __half22float2(*reinterpret_cast<__half2*>(&v.x));
            float2 fd = __half22float2(*reinterpret_cast<__half2*>(&v.y));
            acc.x += fa.x; acc.y += fa.y;
            acc.z += fd.x; acc.w += fd.y;
        }
    }
    float dis = g_dis[node];
    float4 bv = ((const float4*)b)[lane];
    acc.x = acc.x * dis + bv.x; acc.y = acc.y * dis + bv.y;
    acc.z = acc.z * dis + bv.z; acc.w = acc.w * dis + bv.w;
    if (mode) {
        acc.x = fmaxf(acc.x, 0.f); acc.y = fmaxf(acc.y, 0.f);
        acc.z = fmaxf(acc.z, 0.f); acc.w = fmaxf(acc.w, 0.f);
        ((uint2*)o16)[(size_t)node * 32 + lane] =
            make_uint2(pack_h2(acc.x, acc.y), pack_h2(acc.z, acc.w));
    } else {
        ((float4*)outf)[(size_t)node * 32 + lane] = acc;
    }
}

// ------------------------- pooling -----------------------------------------
__device__ __forceinline__ int lower_bound_batch(const int* __restrict__ batch, int g) {
    int lo = 0, hi = N_NODES;
    while (lo < hi) {
        int mid = (lo + hi) >> 1;
        if (batch[mid] < g) lo = mid + 1; else hi = mid;
    }
    return lo;
}

__global__ void k_pool1(const int* __restrict__ batch) {
    int g = blockIdx.x, c = blockIdx.y, t = threadIdx.x;
    int beg = lower_bound_batch(batch, g);
    int end = lower_bound_batch(batch, g + 1);
    int len = end - beg;
    int chunk = (len + POOL_CHUNKS - 1) / POOL_CHUNKS;
    int s = beg + c * chunk;
    int e = min(end, s + chunk);
    float m = -CUDART_INF_F;
    for (int r = s; r < e; r++)
        m = fmaxf(m, g_agg[(size_t)r * D + t]);
    g_pmax[(size_t)(g * POOL_CHUNKS + c) * D + t] = m;
}

__global__ void k_pool2(float* __restrict__ out) {
    int g = blockIdx.x, t = threadIdx.x;
    float m = -CUDART_INF_F;
#pragma unroll
    for (int c = 0; c < POOL_CHUNKS; c++)
        m = fmaxf(m, g_pmax[(size_t)(g * POOL_CHUNKS + c) * D + t]);
    out[(size_t)g * D + t] = m;
}

// ------------------------- launch ------------------------------------------
extern "C" void kernel_launch(void* const* d_in, const int* in_sizes, int n_in,
                              void* d_out, int out_size) {
    const float* x  = (const float*)d_in[0];
    const float* W1 = (const float*)d_in[1];
    const float* b1 = (const float*)d_in[2];
    const float* W2 = (const float*)d_in[3];
    const float* b2 = (const float*)d_in[4];
    const float* W3 = (const float*)d_in[5];
    const float* b3 = (const float*)d_in[6];
    const int* edge_index = (const int*)d_in[7];
    const int* batch = (const int*)d_in[8];
    const int* src = edge_index;
    const int* dst = edge_index + N_EDGES;
    float* out = (float*)d_out;

    uint32_t* h16 = nullptr; cudaGetSymbolAddress((void**)&h16, g_h16);
    uint32_t* a16 = nullptr; cudaGetSymbolAddress((void**)&a16, g_a16);
    float*    agg = nullptr; cudaGetSymbolAddress((void**)&agg, g_agg);
    uint32_t* wbh = nullptr; cudaGetSymbolAddress((void**)&wbh, g_Wbh);
    uint32_t* wbl = nullptr; cudaGetSymbolAddress((void**)&wbl, g_Wbl);

    // side stream + fork/join events, created once on the (uncaptured)
    // correctness call; every call records an identical graph topology.
    static cudaStream_t s2 = nullptr;
    static cudaEvent_t ev_begin = nullptr, ev_dis = nullptr, ev_g1 = nullptr;
    if (s2 == nullptr) {
        cudaStreamCreateWithFlags(&s2, cudaStreamNonBlocking);
        cudaEventCreateWithFlags(&ev_begin, cudaEventDisableTiming);
        cudaEventCreateWithFlags(&ev_dis,   cudaEventDisableTiming);
        cudaEventCreateWithFlags(&ev_g1,    cudaEventDisableTiming);
    }

    const int nthr = 256;
    const int gemm_grid = (N_NODES + 127) / 128;   // 391
    const int agg_grid  = (N_NODES + 7) / 8;
    const int WSZ = 128 * 64;                      // u32 per layer

    // ---- fork: side stream does W-split while main does count/scan
    cudaEventRecord(ev_begin, 0);
    cudaStreamWaitEvent(s2, ev_begin, 0);
    k_splitW<<<(3 * WSZ + nthr - 1) / nthr, nthr, 0, s2>>>(W1, W2, W3);

    // main: CSR chain. g_deg zero on entry (BSS first call; k_scanL re-zeroes).
    k_count <<<(N_EDGES + nthr - 1) / nthr, nthr>>>(dst);
    k_scanL <<<N_SCAN_BLKS, SCAN_BLK>>>();
    cudaEventRecord(ev_dis, 0);                   // g_dis/g_rowoff/g_next ready
    k_fill  <<<(N_EDGES + nthr - 1) / nthr, nthr>>>(src, dst);

    // side: gemm1 (needs splitW + g_dis), overlaps fill
    cudaStreamWaitEvent(s2, ev_dis, 0);
    k_gemm_tc<0><<<gemm_grid, 256, 0, s2>>>(x, wbh, wbl, h16);
    cudaEventRecord(ev_g1, s2);
    cudaStreamWaitEvent(0, ev_g1, 0);             // join

    // serial layer chain on main stream
    k_agg      <<<agg_grid, 256>>>(h16, b1, nullptr, a16, 1);
    k_gemm_tc<1><<<gemm_grid, 256>>>(a16, wbh + WSZ, wbl + WSZ, h16);
    k_agg      <<<agg_grid, 256>>>(h16, b2, nullptr, a16, 1);
    k_gemm_tc<1><<<gemm_grid, 256>>>(a16, wbh + 2 * WSZ, wbl + 2 * WSZ, h16);
    k_agg      <<<agg_grid, 256>>>(h16, b3, agg, nullptr, 0);

    k_pool1<<<dim3(N_GRAPHS, POOL_CHUNKS), D>>>(batch);
    k_pool2<<<N_GRAPHS, D>>>(out);
}